// round 6
// baseline (speedup 1.0000x reference)
#include <cuda_runtime.h>
#include <math.h>
#include <stdint.h>

#define B_    64
#define T_    1000
#define D_    512
#define V_    29
#define L_    200
#define S_    401            // 2*L + 1
#define CBLANK 28
#define NEGV  (-1e9f)
#define LOG2E 1.44269504088896340736f
#define LN2   0.69314718055994530942f

typedef unsigned long long u64;

// ---------------- device scratch (no allocations allowed) ----------------
__device__ float d_lp[(long)B_ * T_ * V_];   // LOG2-probs lp2[b][t][v], 7.4 MB
__device__ float d_loss[B_];

__device__ __forceinline__ float ex2f(float x){ float r; asm("ex2.approx.f32 %0, %1;" : "=f"(r) : "f"(x)); return r; }
__device__ __forceinline__ float lg2f(float x){ float r; asm("lg2.approx.f32 %0, %1;" : "=f"(r) : "f"(x)); return r; }

// exact 3-way log2-sum-exp via selects (no cancellation; NEGV-safe)
__device__ __forceinline__ float lse3(float a0, float a1, float a2)
{
    const float mab = fmaxf(a0, a1);
    const float nab = fminf(a0, a1);
    const float mx  = fmaxf(mab, a2);
    const float mn  = fminf(nab, a2);
    const float md  = fmaxf(nab, fminf(mab, a2));
    return mx + lg2f(1.0f + ex2f(mn - mx) + ex2f(md - mx));
}

#define FMA2(d, a, b) asm("fma.rn.f32x2 %0, %1, %2, %0;" : "+l"(d) : "l"(a), "l"(b))

// =====================================================================
// Kernel 1: PROVEN R3 GEMM (verbatim). logits = F @ W + b, log2_softmax.
// 128 threads, 128 rows/block, thread tile 8 rows x 4 cols, FFMA2 over
// row-pairs with duplicated W.
// =====================================================================
#define BM      128
#define KC      32
#define FSTRIDE 132

__global__ __launch_bounds__(128) void gemm_lsm_kernel(
    const float* __restrict__ F, const float* __restrict__ W,
    const float* __restrict__ bias)
{
    __shared__ float fbuf[KC * FSTRIDE];   // 4224 floats; reused as logits [128][33]
    __shared__ float wdup[KC * 32 * 2];    // duplicated (w,w) pairs
    __shared__ float csh[BM];              // per-row (max + log(sumexp))

    const int tid  = threadIdx.x;
    const long rowBase = (long)blockIdx.x * BM;
    const float* Fb = F + rowBase * D_;

    const int cg   = tid & 7;
    const int rg   = tid >> 3;
    const int col0 = cg * 4;
    const int row0 = rg * 8;

    u64 acc[4][4];
#pragma unroll
    for (int p = 0; p < 4; p++)
#pragma unroll
        for (int j = 0; j < 4; j++) acc[p][j] = 0ull;

    for (int kc = 0; kc < D_; kc += KC) {
        for (int i = tid; i < KC * 32; i += 128) {
            int k = i >> 5, v = i & 31;
            float w = (v < V_) ? W[(long)(kc + k) * V_ + v] : 0.f;
            wdup[2 * i] = w; wdup[2 * i + 1] = w;
        }
        {
            const int kk = (tid & 7) * 4;
            for (int r = (tid >> 3); r < BM; r += 16) {
                float4 v = *reinterpret_cast<const float4*>(Fb + (long)r * D_ + kc + kk);
                fbuf[(kk + 0) * FSTRIDE + r] = v.x;
                fbuf[(kk + 1) * FSTRIDE + r] = v.y;
                fbuf[(kk + 2) * FSTRIDE + r] = v.z;
                fbuf[(kk + 3) * FSTRIDE + r] = v.w;
            }
        }
        __syncthreads();

#pragma unroll
        for (int k = 0; k < KC; k++) {
            const ulonglong2* fp = reinterpret_cast<const ulonglong2*>(&fbuf[k * FSTRIDE + row0]);
            const ulonglong2 fa = fp[0], fb2 = fp[1];
            const ulonglong2* wp = reinterpret_cast<const ulonglong2*>(&wdup[(k * 32 + col0) * 2]);
            const ulonglong2 wa = wp[0], wb2 = wp[1];
            const u64 fr[4] = {fa.x, fa.y, fb2.x, fb2.y};
            const u64 wr[4] = {wa.x, wa.y, wb2.x, wb2.y};
#pragma unroll
            for (int p = 0; p < 4; p++)
#pragma unroll
                for (int j = 0; j < 4; j++)
                    FMA2(acc[p][j], fr[p], wr[j]);
        }
        __syncthreads();
    }

    float bv[4];
#pragma unroll
    for (int j = 0; j < 4; j++) bv[j] = (col0 + j < V_) ? bias[col0 + j] : 0.f;
#pragma unroll
    for (int p = 0; p < 4; p++)
#pragma unroll
        for (int j = 0; j < 4; j++) {
            float lo = __uint_as_float((unsigned)(acc[p][j] & 0xffffffffull));
            float hi = __uint_as_float((unsigned)(acc[p][j] >> 32));
            fbuf[(row0 + 2 * p    ) * 33 + col0 + j] = lo + bv[j];
            fbuf[(row0 + 2 * p + 1) * 33 + col0 + j] = hi + bv[j];
        }
    __syncthreads();

    {
        const float* r = &fbuf[tid * 33];
        float m = r[0];
#pragma unroll
        for (int v = 1; v < V_; v++) m = fmaxf(m, r[v]);
        float sum = 0.f;
#pragma unroll
        for (int v = 0; v < V_; v++) sum += ex2f((r[v] - m) * LOG2E);
        csh[tid] = m + lg2f(sum) * LN2;
    }
    __syncthreads();

    float* outp = d_lp + rowBase * V_;
    for (int i = tid; i < BM * V_; i += 128) {
        int row = i / V_;
        int v   = i - row * V_;
        outp[i] = (fbuf[row * 33 + v] - csh[row]) * LOG2E;
    }
}

// =====================================================================
// Kernel 2: CTC alpha recursion, LOG2 domain, 2 STEPS PER BARRIER.
// (R5 version, verbatim.) One block per batch, 416 threads, thread s
// owns state s. Lanes 0/1 redundantly compute states 32w-2 / 32w-1 at
// step t so step t+1 needs no fresh cross-warp data. Deterministic.
// =====================================================================
__global__ __launch_bounds__(416) void ctc_kernel(
    const int* __restrict__ labels, const int* __restrict__ flens,
    const int* __restrict__ llens)
{
    __shared__ float abuf[2][420];      // idx = state + 4; pads [0..3] = NEGV
    __shared__ int   lab_sh[L_];
    __shared__ float afin[416];

    const int b    = blockIdx.x;
    const int tid  = threadIdx.x;
    const int w    = tid >> 5;
    const int lane = tid & 31;
    const int flen = flens[b];
    const int llen = llens[b];
    const unsigned FULL = 0xffffffffu;

    for (int i = tid; i < L_; i += 416) lab_sh[i] = labels[b * L_ + i];
    if (tid < 4) { abuf[0][tid] = NEGV; abuf[1][tid] = NEGV; }
    __syncthreads();

    const int s = tid;
    int   ext  = CBLANK;
    bool  skip = false;
    if (s < S_ && (s & 1)) {
        const int j = s >> 1;
        ext  = lab_sh[j];
        skip = (s >= 3) ? (ext != lab_sh[j - 1]) : true;
    }
    int   extv  = ext;
    bool  skipv = false;
    if (lane == 1 && w > 0) {
        const int jv = 16 * w - 1;
        extv  = lab_sh[jv];
        skipv = (extv != lab_sh[jv - 1]);
    }

    const float* lpb = d_lp + (long)b * T_ * V_;

    float myA = NEGV;
    if (s == 0) myA = lpb[CBLANK];
    else if (s == 1) myA = lpb[ext];
    abuf[0][s + 4] = myA;

    float pf_s0 = lpb[1 * V_ + ext];
    float pf_s1 = lpb[2 * V_ + ext];
    float pf_s2 = lpb[3 * V_ + ext];
    float pf_s3 = lpb[4 * V_ + ext];
    float pf_v0 = lpb[1 * V_ + extv];
    float pf_v1 = lpb[3 * V_ + extv];
    __syncthreads();

    int cur = 0;
    int t = 1;
    for (; t + 1 < flen; t += 2) {
        const float* bnd0 = &abuf[cur][32 * w];

        // ---- step t ----
        float am1 = __shfl_up_sync(FULL, myA, 1);
        float am2 = __shfl_up_sync(FULL, myA, 2);
        float am3 = __shfl_up_sync(FULL, myA, 3);
        float am4 = __shfl_up_sync(FULL, myA, 4);
        if (lane == 0) { am1 = bnd0[3]; am2 = bnd0[2]; am3 = bnd0[1]; }
        if (lane == 1) { am2 = bnd0[3]; am3 = bnd0[2]; am4 = bnd0[1]; }

        const float x  = lse3(myA, am1, skip  ? am2 : NEGV) + pf_s0;
        const float vv = lse3(am2, am3, skipv ? am4 : NEGV) + pf_v0;

        // ---- step t+1 ----
        float bm1 = __shfl_up_sync(FULL, x, 1);
        float bm2 = __shfl_up_sync(FULL, x, 2);
        const float vb = __shfl_sync(FULL, vv, 1);
        if (lane == 0) { bm1 = vb; bm2 = vv; }
        if (lane == 1) { bm2 = vv; }

        myA = lse3(x, bm1, skip ? bm2 : NEGV) + pf_s1;
        abuf[cur ^ 1][s + 4] = myA;
        cur ^= 1;

        pf_s0 = pf_s2; pf_s1 = pf_s3; pf_v0 = pf_v1;
        const int r4 = min(t + 4, T_ - 1) * V_;
        const int r5 = min(t + 5, T_ - 1) * V_;
        pf_s2 = lpb[r4 + ext];
        pf_s3 = lpb[r5 + ext];
        pf_v1 = lpb[r4 + extv];

        __syncthreads();
    }

    if (t < flen) {
        const float* bnd0 = &abuf[cur][32 * w];
        float am1 = __shfl_up_sync(FULL, myA, 1);
        float am2 = __shfl_up_sync(FULL, myA, 2);
        if (lane == 0) { am1 = bnd0[3]; am2 = bnd0[2]; }
        if (lane == 1) { am2 = bnd0[3]; }
        myA = lse3(myA, am1, skip ? am2 : NEGV) + pf_s0;
    }

    __syncthreads();
    afin[tid] = myA;
    __syncthreads();

    if (tid == 0) {
        const float l1 = afin[2 * llen];
        const float l2 = afin[2 * llen - 1];
        const float mx = fmaxf(l1, l2), mn = fminf(l1, l2);
        const float ls = mx + lg2f(1.0f + ex2f(mn - mx));
        const float nll = -ls * LN2;
        d_loss[b] = (nll < 5e8f) ? nll / (float)llen : 0.f;
    }
}

// =====================================================================
// Kernel 3: deterministic fixed-order mean of 64 losses
// =====================================================================
__global__ void reduce_kernel(float* __restrict__ out)
{
    const int lane = threadIdx.x;
    float v = d_loss[lane] + d_loss[lane + 32];
#pragma unroll
    for (int o = 16; o > 0; o >>= 1) v += __shfl_down_sync(0xffffffffu, v, o);
    if (lane == 0) out[0] = v * (1.f / (float)B_);
}

// =====================================================================
extern "C" void kernel_launch(void* const* d_in, const int* in_sizes, int n_in,
                              void* d_out, int out_size)
{
    (void)in_sizes; (void)n_in; (void)out_size;
    const float* F      = (const float*)d_in[0];
    const float* W      = (const float*)d_in[1];
    const float* bias   = (const float*)d_in[2];
    const int*   labels = (const int*)d_in[3];
    const int*   flens  = (const int*)d_in[4];
    const int*   llens  = (const int*)d_in[5];
    float* out = (float*)d_out;

    gemm_lsm_kernel<<<(B_ * T_) / BM, 128>>>(F, W, bias);
    ctc_kernel<<<B_, 416>>>(labels, flens, llens);
    reduce_kernel<<<1, 32>>>(out);
}